// round 13
// baseline (speedup 1.0000x reference)
#include <cuda_runtime.h>
#include <cuda_fp16.h>
#include <cstdint>

#define T_SEQ 2048
#define NB 2
#define DIM 1024
#define NH 16
#define HS 64
#define NT_ROWS 4096
#define NEG_INF_F (-1e9f)
#define NELEM (NT_ROWS * DIM)

// ---------------- scratch (__device__ globals: allocation-free rule) --------
__device__ __half g_Xq16[NELEM];
__device__ __half g_Xr16[NELEM];
__device__ __half g_WqT[DIM * DIM];
__device__ __half g_WkT[DIM * DIM];
__device__ __half g_WvT[DIM * DIM];
__device__ __half g_WoT[DIM * DIM];
__device__ __half g_Q16[NELEM];
__device__ __half g_K16[NELEM];
__device__ __half g_V16[NELEM];
__device__ __half g_Vt16[NELEM];
__device__ __half g_O16[NELEM];

// ---------------- helpers ---------------------------------------------------
__device__ __forceinline__ unsigned pkh(__half a, __half b) {
    return (unsigned)__half_as_ushort(a) | ((unsigned)__half_as_ushort(b) << 16);
}
__device__ __forceinline__ unsigned pk2(float x0, float x1) {
    __half2 h = __float22half2_rn(make_float2(x0, x1));
    return *(unsigned*)&h;
}
__device__ __forceinline__ void mma16816h(float (&d)[4], const unsigned (&a)[4],
                                          unsigned b0, unsigned b1) {
    asm volatile(
        "mma.sync.aligned.m16n8k16.row.col.f32.f16.f16.f32 "
        "{%0,%1,%2,%3}, {%4,%5,%6,%7}, {%8,%9}, {%0,%1,%2,%3};"
        : "+f"(d[0]), "+f"(d[1]), "+f"(d[2]), "+f"(d[3])
        : "r"(a[0]), "r"(a[1]), "r"(a[2]), "r"(a[3]), "r"(b0), "r"(b1));
}
__device__ __forceinline__ uint32_t smem_u32(const void* p) {
    uint32_t a;
    asm("{ .reg .u64 t; cvta.to.shared.u64 t, %1; cvt.u32.u64 %0, t; }" : "=r"(a) : "l"(p));
    return a;
}
__device__ __forceinline__ void cp16(void* smem_dst, const void* gsrc) {
    uint32_t s = smem_u32(smem_dst);
    asm volatile("cp.async.cg.shared.global [%0], [%1], 16;" :: "r"(s), "l"(gsrc) : "memory");
}
#define CP_COMMIT() asm volatile("cp.async.commit_group;" ::: "memory")
#define CP_WAIT2() asm volatile("cp.async.wait_group 2;" ::: "memory")

// ---------------- split kernels ----------------------------------------------
__global__ __launch_bounds__(256) void split_x_all(
    const float* __restrict__ Xq, const float* __restrict__ Xr,
    __half* __restrict__ Xq16, __half* __restrict__ Xr16) {
    const int z = blockIdx.y;
    const float* X = z ? Xr : Xq;
    __half* Xo = z ? Xr16 : Xq16;
    size_t i = ((size_t)blockIdx.x * 256 + threadIdx.x) * 4;
    float4 v = *(const float4*)(X + i);
    *(unsigned*)&Xo[i]     = pk2(v.x, v.y);
    *(unsigned*)&Xo[i + 2] = pk2(v.z, v.w);
}

__global__ __launch_bounds__(256) void split_wT_all(
    const float* __restrict__ W0, const float* __restrict__ W1,
    const float* __restrict__ W2, const float* __restrict__ W3,
    __half* __restrict__ T0, __half* __restrict__ T1,
    __half* __restrict__ T2, __half* __restrict__ T3) {
    const int z = blockIdx.z;
    const float* W = (z == 0) ? W0 : (z == 1) ? W1 : (z == 2) ? W2 : W3;
    __half* Wt = (z == 0) ? T0 : (z == 1) ? T1 : (z == 2) ? T2 : T3;
    __shared__ float S[32][33];
    const int n0 = blockIdx.x * 32, k0 = blockIdx.y * 32;
    const int tid = threadIdx.x;
#pragma unroll
    for (int i = tid; i < 1024; i += 256) {
        int r = i >> 5, c = i & 31;
        S[r][c] = W[(size_t)(k0 + r) * DIM + n0 + c];
    }
    __syncthreads();
#pragma unroll
    for (int i = tid; i < 1024; i += 256) {
        int rr = i >> 5, cc = i & 31;
        Wt[(size_t)(n0 + rr) * DIM + k0 + cc] = __float2half_rn(S[cc][rr]);
    }
}

__global__ __launch_bounds__(256) void transpose_v(const __half* __restrict__ V,
                                                   __half* __restrict__ Vt) {
    __shared__ __half S[64][66];
    const int tt = blockIdx.x, bh = blockIdx.y;
    const int b = bh >> 4, h = bh & 15;
    const int tid = threadIdx.x;
#pragma unroll
    for (int i = tid; i < 64 * 32; i += 256) {
        int r = i >> 5, c2 = (i & 31) * 2;
        size_t g = (size_t)(b * T_SEQ + tt * 64 + r) * DIM + h * HS + c2;
        *(unsigned*)&S[r][c2] = *(const unsigned*)&V[g];
    }
    __syncthreads();
#pragma unroll
    for (int i = tid; i < 64 * 32; i += 256) {
        int s = i >> 5, t2 = (i & 31) * 2;
        size_t g = (size_t)(bh * HS + s) * T_SEQ + tt * 64 + t2;
        *(unsigned*)&Vt[g] = pkh(S[t2][s], S[t2 + 1][s]);
    }
}

// ---------------- single-fp16 GEMM: 128x128x32, 256 thr, 2 CTAs/SM -----------
#define GP 40
#define GEMM_NKT 32
#define GEMM_STAGE (256 * GP)               // A 128 rows + B 128 rows
#define GEMM_SMEM (3 * GEMM_STAGE * 2)      // 61440 B (x2 CTAs = 122880)

__device__ __forceinline__ void gemm_body(
    const __half* __restrict__ A_, const __half* __restrict__ B_,
    float* __restrict__ Cf, __half* __restrict__ Ch, int mode, float scale,
    __half* gsm, int bm, int bn) {
    const int tid = threadIdx.x;
    const int lane = tid & 31, wid = tid >> 5;
    const int gid = lane >> 2, tig = lane & 3;
    const int wm = (wid & 3) * 32, wn = (wid >> 2) * 64;

    auto load_stage = [&](int stage, int kt) {
        const int k0 = kt * 32;
        __half* sb = gsm + stage * GEMM_STAGE;
#pragma unroll
        for (int i = tid; i < 1024; i += 256) {
            int r = i >> 2, c = i & 3;
            const __half* src = (r < 128)
                ? A_ + (size_t)(bm + r) * DIM + k0 + c * 8
                : B_ + (size_t)(bn + r - 128) * DIM + k0 + c * 8;
            cp16(sb + r * GP + c * 8, src);
        }
    };

    float acc[2][8][4];
#pragma unroll
    for (int mt = 0; mt < 2; mt++)
#pragma unroll
        for (int jn = 0; jn < 8; jn++)
#pragma unroll
            for (int e = 0; e < 4; e++) acc[mt][jn][e] = 0.f;

    load_stage(0, 0); CP_COMMIT();
    load_stage(1, 1); CP_COMMIT();

    for (int kt = 0; kt < GEMM_NKT; kt++) {
        if (kt + 2 < GEMM_NKT) load_stage((kt + 2) % 3, kt + 2);
        CP_COMMIT();
        CP_WAIT2();
        __syncthreads();

        const __half* st = gsm + (kt % 3) * GEMM_STAGE;
        const __half* As = st;
        const __half* Bs = st + 128 * GP;
#pragma unroll
        for (int kk = 0; kk < 2; kk++) {
            const int kc = kk * 16 + 2 * tig;
            unsigned af[2][4];
#pragma unroll
            for (int mt = 0; mt < 2; mt++) {
                int row = wm + 16 * mt + gid;
                af[mt][0] = *(const unsigned*)&As[row * GP + kc];
                af[mt][1] = *(const unsigned*)&As[(row + 8) * GP + kc];
                af[mt][2] = *(const unsigned*)&As[row * GP + kc + 8];
                af[mt][3] = *(const unsigned*)&As[(row + 8) * GP + kc + 8];
            }
#pragma unroll
            for (int jn = 0; jn < 8; jn++) {
                int n = wn + 8 * jn + gid;
                unsigned b0 = *(const unsigned*)&Bs[n * GP + kc];
                unsigned b1 = *(const unsigned*)&Bs[n * GP + kc + 8];
#pragma unroll
                for (int mt = 0; mt < 2; mt++)
                    mma16816h(acc[mt][jn], af[mt], b0, b1);
            }
        }
        __syncthreads();
    }

#pragma unroll
    for (int mt = 0; mt < 2; mt++) {
        int row0 = bm + wm + 16 * mt + gid;
#pragma unroll
        for (int jn = 0; jn < 8; jn++) {
            int col = bn + wn + 8 * jn + 2 * tig;
            float x0 = acc[mt][jn][0] * scale, x1 = acc[mt][jn][1] * scale;
            float x2 = acc[mt][jn][2] * scale, x3 = acc[mt][jn][3] * scale;
            if (mode == 0) {
                *(float2*)&Cf[(size_t)row0 * DIM + col] = make_float2(x0, x1);
                *(float2*)&Cf[(size_t)(row0 + 8) * DIM + col] = make_float2(x2, x3);
            } else {
                *(unsigned*)&Ch[(size_t)row0 * DIM + col] = pk2(x0, x1);
                *(unsigned*)&Ch[(size_t)(row0 + 8) * DIM + col] = pk2(x2, x3);
            }
        }
    }
}

__global__ __launch_bounds__(256, 2) void gemm_mma(
    const __half* __restrict__ A_, const __half* __restrict__ B_,
    float* __restrict__ Cf, __half* __restrict__ Ch, int mode, float scale) {
    extern __shared__ __half gsm[];
    gemm_body(A_, B_, Cf, Ch, mode, scale, gsm,
              blockIdx.y * 128, blockIdx.x * 128);
}

// merged K/V projection: z = 0 -> K = Xr@Wk ; z = 1 -> V = Xr@Wv
__global__ __launch_bounds__(256, 2) void gemm_kv(
    const __half* __restrict__ Xr_, const __half* __restrict__ WkT_,
    const __half* __restrict__ WvT_, __half* __restrict__ K_,
    __half* __restrict__ V_) {
    extern __shared__ __half gsm2[];
    const int z = blockIdx.z;
    gemm_body(Xr_, z ? WvT_ : WkT_, nullptr, z ? V_ : K_, 2, 1.0f, gsm2,
              blockIdx.y * 128, blockIdx.x * 128);
}

// ---------------- flash attention: single fp16, 1 sync/iter ------------------
#define AP 72
#define ATTN_NKT (T_SEQ / 64)
#define KV_STAGE (2 * 64 * AP)
#define ATTN_SMEM ((128 * AP + 4 * KV_STAGE) * 2)    // 92160 B

__global__ __launch_bounds__(256, 2) void attn_mma(
    const __half* __restrict__ Q_, const __half* __restrict__ K_,
    const __half* __restrict__ Vt_, const float* __restrict__ mask,
    __half* __restrict__ O_) {
    extern __shared__ __half asm_[];
    __half* Qs = asm_;
    __half* KV = Qs + 128 * AP;

    const int tid = threadIdx.x;
    const int lane = tid & 31, wid = tid >> 5;
    const int gid = lane >> 2, tig = lane & 3;
    const int bq = blockIdx.x, h = blockIdx.y, b = blockIdx.z;
    const int bh = b * NH + h;
    const int qrow0 = b * T_SEQ + bq * 128;

    auto load_kv = [&](int stage, int kt) {
        const int krow0 = b * T_SEQ + kt * 64;
        __half* sb = KV + stage * KV_STAGE;
#pragma unroll
        for (int i = tid; i < 1024; i += 256) {
            int a = i >> 9, r = (i >> 3) & 63, c = i & 7;
            __half* dst = sb + a * 64 * AP + r * AP + c * 8;
            if (a == 0)
                cp16(dst, K_ + (size_t)(krow0 + r) * DIM + h * HS + c * 8);
            else
                cp16(dst, Vt_ + (size_t)(bh * HS + r) * T_SEQ + kt * 64 + c * 8);
        }
    };

#pragma unroll
    for (int i = tid; i < 128 * 8; i += 256) {
        int r = i >> 3, c8 = (i & 7) * 8;
        *(int4*)&Qs[r * AP + c8] =
            *(const int4*)&Q_[(size_t)(qrow0 + r) * DIM + h * HS + c8];
    }

    load_kv(0, 0); CP_COMMIT();
    load_kv(1, 1); CP_COMMIT();
    load_kv(2, 2); CP_COMMIT();

    float li[2] = {0.f, 0.f};
    float accO[8][4];
#pragma unroll
    for (int jn = 0; jn < 8; jn++)
#pragma unroll
        for (int e = 0; e < 4; e++) accO[jn][e] = 0.f;

    const int q0g = bq * 128 + 16 * wid + gid;
    const float* mrow = mask + (size_t)bh * T_SEQ * T_SEQ;
    __syncthreads();   // Q visible

    for (int kt = 0; kt < ATTN_NKT; kt++) {
        // mask prefetch first: LDGs in flight across the pipeline wait
        float2 mr0[8], mr1[8];
#pragma unroll
        for (int jn = 0; jn < 8; jn++) {
            int c = kt * 64 + 8 * jn + 2 * tig;
            mr0[jn] = *(const float2*)&mrow[(size_t)q0g * T_SEQ + c];
            mr1[jn] = *(const float2*)&mrow[(size_t)(q0g + 8) * T_SEQ + c];
        }

        CP_WAIT2();        // buffer kt complete (kt+1, kt+2 may still pend)
        __syncthreads();   // SINGLE barrier: also proves all warps done with kt-1

        // safe to overwrite buffer (kt+3)&3 == (kt-1)&3 now
        if (kt + 3 < ATTN_NKT) load_kv((kt + 3) & 3, kt + 3);
        CP_COMMIT();

        const __half* K_s = KV + (kt & 3) * KV_STAGE;
        const __half* V_s = K_s + 64 * AP;

        float sc[8][4];
#pragma unroll
        for (int jn = 0; jn < 8; jn++)
#pragma unroll
            for (int e = 0; e < 4; e++) sc[jn][e] = 0.f;
#pragma unroll
        for (int kk = 0; kk < 4; kk++) {
            const int kc = kk * 16 + 2 * tig;
            const int row = 16 * wid + gid;
            unsigned qa[4];
            qa[0] = *(const unsigned*)&Qs[row * AP + kc];
            qa[1] = *(const unsigned*)&Qs[(row + 8) * AP + kc];
            qa[2] = *(const unsigned*)&Qs[row * AP + kc + 8];
            qa[3] = *(const unsigned*)&Qs[(row + 8) * AP + kc + 8];
#pragma unroll
            for (int jn = 0; jn < 8; jn++) {
                int n = 8 * jn + gid;
                unsigned kf0 = *(const unsigned*)&K_s[n * AP + kc];
                unsigned kf1 = *(const unsigned*)&K_s[n * AP + kc + 8];
                mma16816h(sc[jn], qa, kf0, kf1);
            }
        }

        // mask + exp (max-free; masked scores underflow to 0)
        float rs0 = 0.f, rs1 = 0.f;
#pragma unroll
        for (int jn = 0; jn < 8; jn++) {
            sc[jn][0] = __expf(fmaf(mr0[jn].x, NEG_INF_F, sc[jn][0])); rs0 += sc[jn][0];
            sc[jn][1] = __expf(fmaf(mr0[jn].y, NEG_INF_F, sc[jn][1])); rs0 += sc[jn][1];
            sc[jn][2] = __expf(fmaf(mr1[jn].x, NEG_INF_F, sc[jn][2])); rs1 += sc[jn][2];
            sc[jn][3] = __expf(fmaf(mr1[jn].y, NEG_INF_F, sc[jn][3])); rs1 += sc[jn][3];
        }
        rs0 += __shfl_xor_sync(0xffffffffu, rs0, 1);
        rs0 += __shfl_xor_sync(0xffffffffu, rs0, 2);
        rs1 += __shfl_xor_sync(0xffffffffu, rs1, 1);
        rs1 += __shfl_xor_sync(0xffffffffu, rs1, 2);
        li[0] += rs0;
        li[1] += rs1;

        // accO += P @ V
#pragma unroll
        for (int kk2 = 0; kk2 < 4; kk2++) {
            const int j0 = 2 * kk2, j1 = 2 * kk2 + 1;
            unsigned pa[4];
            pa[0] = pk2(sc[j0][0], sc[j0][1]);
            pa[1] = pk2(sc[j0][2], sc[j0][3]);
            pa[2] = pk2(sc[j1][0], sc[j1][1]);
            pa[3] = pk2(sc[j1][2], sc[j1][3]);
            const int kc = kk2 * 16 + 2 * tig;
#pragma unroll
            for (int jn = 0; jn < 8; jn++) {
                int n = 8 * jn + gid;
                unsigned vf0 = *(const unsigned*)&V_s[n * AP + kc];
                unsigned vf1 = *(const unsigned*)&V_s[n * AP + kc + 8];
                mma16816h(accO[jn], pa, vf0, vf1);
            }
        }
        // no end-of-iteration barrier: next iteration's top barrier protects reuse
    }

    const float inv0 = 1.f / li[0], inv1 = 1.f / li[1];
    const int row0 = qrow0 + 16 * wid + gid;
#pragma unroll
    for (int jn = 0; jn < 8; jn++) {
        int col = h * HS + 8 * jn + 2 * tig;
        *(unsigned*)&O_[(size_t)row0 * DIM + col] =
            pk2(accO[jn][0] * inv0, accO[jn][1] * inv0);
        *(unsigned*)&O_[(size_t)(row0 + 8) * DIM + col] =
            pk2(accO[jn][2] * inv1, accO[jn][3] * inv1);
    }
}

// ---------------------------------------------------------------------------
extern "C" void kernel_launch(void* const* d_in, const int* in_sizes, int n_in,
                              void* d_out, int out_size) {
    const float* Xq   = (const float*)d_in[0];
    const float* Xr   = (const float*)d_in[1];
    const float* mask = (const float*)d_in[2];
    const float* Wq   = (const float*)d_in[3];
    const float* Wk   = (const float*)d_in[4];
    const float* Wv   = (const float*)d_in[5];
    const float* Wo   = (const float*)d_in[6];
    float* out = (float*)d_out;

    __half *Xq16, *Xr16, *WqT, *WkT, *WvT, *WoT;
    __half *Q16, *K16, *V16, *Vt16, *O16;
    cudaGetSymbolAddress((void**)&Xq16, g_Xq16); cudaGetSymbolAddress((void**)&Xr16, g_Xr16);
    cudaGetSymbolAddress((void**)&WqT, g_WqT);   cudaGetSymbolAddress((void**)&WkT, g_WkT);
    cudaGetSymbolAddress((void**)&WvT, g_WvT);   cudaGetSymbolAddress((void**)&WoT, g_WoT);
    cudaGetSymbolAddress((void**)&Q16, g_Q16);   cudaGetSymbolAddress((void**)&K16, g_K16);
    cudaGetSymbolAddress((void**)&V16, g_V16);   cudaGetSymbolAddress((void**)&Vt16, g_Vt16);
    cudaGetSymbolAddress((void**)&O16, g_O16);

    cudaFuncSetAttribute(attn_mma, cudaFuncAttributeMaxDynamicSharedMemorySize, ATTN_SMEM);
    cudaFuncSetAttribute(gemm_mma, cudaFuncAttributeMaxDynamicSharedMemorySize, GEMM_SMEM);
    cudaFuncSetAttribute(gemm_kv, cudaFuncAttributeMaxDynamicSharedMemorySize, GEMM_SMEM);

    dim3 gg(DIM / 128, NT_ROWS / 128);          // (8, 32) = 256 CTAs, 2/SM
    dim3 ggkv(DIM / 128, NT_ROWS / 128, 2);     // K and V in one launch

    split_x_all<<<dim3(NELEM / 1024, 2), 256>>>(Xq, Xr, Xq16, Xr16);
    split_wT_all<<<dim3(32, 32, 4), 256>>>(Wq, Wk, Wv, Wo, WqT, WkT, WvT, WoT);
    gemm_kv<<<ggkv, 256, GEMM_SMEM>>>(Xr16, WkT, WvT, K16, V16);
    transpose_v<<<dim3(T_SEQ / 64, NB * NH), 256>>>(V16, Vt16);
    gemm_mma<<<gg, 256, GEMM_SMEM>>>(Xq16, WqT, nullptr, Q16, 2, 0.125f);
    attn_mma<<<dim3(T_SEQ / 128, NH, NB), 256, ATTN_SMEM>>>(
        Q16, K16, Vt16, mask, O16);
    gemm_mma<<<gg, 256, GEMM_SMEM>>>(O16, WoT, out, nullptr, 0, 1.0f);
}

// round 15
// speedup vs baseline: 1.4251x; 1.4251x over previous
#include <cuda_runtime.h>
#include <cuda_fp16.h>
#include <cstdint>

#define T_SEQ 2048
#define NB 2
#define DIM 1024
#define NH 16
#define HS 64
#define NT_ROWS 4096
#define NEG_INF_F (-1e9f)
#define NELEM (NT_ROWS * DIM)

// ---------------- scratch (__device__ globals: allocation-free rule) --------
__device__ __half g_Xq16[NELEM];
__device__ __half g_Xr16[NELEM];
__device__ __half g_WqT[DIM * DIM];
__device__ __half g_WkT[DIM * DIM];
__device__ __half g_WvT[DIM * DIM];
__device__ __half g_WoT[DIM * DIM];
__device__ __half g_Q16[NELEM];
__device__ __half g_K16[NELEM];
__device__ __half g_V16[NELEM];
__device__ __half g_Vt16[NELEM];
__device__ __half g_O16[NELEM];

// ---------------- helpers ---------------------------------------------------
__device__ __forceinline__ unsigned pkh(__half a, __half b) {
    return (unsigned)__half_as_ushort(a) | ((unsigned)__half_as_ushort(b) << 16);
}
__device__ __forceinline__ unsigned pk2(float x0, float x1) {
    __half2 h = __float22half2_rn(make_float2(x0, x1));   // one cvt.rn.f16x2.f32
    return *(unsigned*)&h;
}
__device__ __forceinline__ void mma16816h(float (&d)[4], const unsigned (&a)[4],
                                          unsigned b0, unsigned b1) {
    asm volatile(
        "mma.sync.aligned.m16n8k16.row.col.f32.f16.f16.f32 "
        "{%0,%1,%2,%3}, {%4,%5,%6,%7}, {%8,%9}, {%0,%1,%2,%3};"
        : "+f"(d[0]), "+f"(d[1]), "+f"(d[2]), "+f"(d[3])
        : "r"(a[0]), "r"(a[1]), "r"(a[2]), "r"(a[3]), "r"(b0), "r"(b1));
}
__device__ __forceinline__ uint32_t smem_u32(const void* p) {
    uint32_t a;
    asm("{ .reg .u64 t; cvta.to.shared.u64 t, %1; cvt.u32.u64 %0, t; }" : "=r"(a) : "l"(p));
    return a;
}
__device__ __forceinline__ void cp16(void* smem_dst, const void* gsrc) {
    uint32_t s = smem_u32(smem_dst);
    asm volatile("cp.async.cg.shared.global [%0], [%1], 16;" :: "r"(s), "l"(gsrc) : "memory");
}
#define CP_COMMIT() asm volatile("cp.async.commit_group;" ::: "memory")
#define CP_WAIT2() asm volatile("cp.async.wait_group 2;" ::: "memory")
#define CP_WAIT3() asm volatile("cp.async.wait_group 3;" ::: "memory")

// ---------------- split kernels ----------------------------------------------
__global__ __launch_bounds__(256) void split_x_all(
    const float* __restrict__ Xq, const float* __restrict__ Xr,
    __half* __restrict__ Xq16, __half* __restrict__ Xr16) {
    const int z = blockIdx.y;
    const float* X = z ? Xr : Xq;
    __half* Xo = z ? Xr16 : Xq16;
    size_t i = ((size_t)blockIdx.x * 256 + threadIdx.x) * 4;
    float4 v = *(const float4*)(X + i);
    *(unsigned*)&Xo[i]     = pk2(v.x, v.y);
    *(unsigned*)&Xo[i + 2] = pk2(v.z, v.w);
}

__global__ __launch_bounds__(256) void split_wT_all(
    const float* __restrict__ W0, const float* __restrict__ W1,
    const float* __restrict__ W2, const float* __restrict__ W3,
    __half* __restrict__ T0, __half* __restrict__ T1,
    __half* __restrict__ T2, __half* __restrict__ T3) {
    const int z = blockIdx.z;
    const float* W = (z == 0) ? W0 : (z == 1) ? W1 : (z == 2) ? W2 : W3;
    __half* Wt = (z == 0) ? T0 : (z == 1) ? T1 : (z == 2) ? T2 : T3;
    __shared__ float S[32][33];
    const int n0 = blockIdx.x * 32, k0 = blockIdx.y * 32;
    const int tid = threadIdx.x;
#pragma unroll
    for (int i = tid; i < 1024; i += 256) {
        int r = i >> 5, c = i & 31;
        S[r][c] = W[(size_t)(k0 + r) * DIM + n0 + c];
    }
    __syncthreads();
#pragma unroll
    for (int i = tid; i < 1024; i += 256) {
        int rr = i >> 5, cc = i & 31;
        Wt[(size_t)(n0 + rr) * DIM + k0 + cc] = __float2half_rn(S[cc][rr]);
    }
}

__global__ __launch_bounds__(256) void transpose_v(const __half* __restrict__ V,
                                                   __half* __restrict__ Vt) {
    __shared__ __half S[64][66];
    const int tt = blockIdx.x, bh = blockIdx.y;
    const int b = bh >> 4, h = bh & 15;
    const int tid = threadIdx.x;
#pragma unroll
    for (int i = tid; i < 64 * 32; i += 256) {
        int r = i >> 5, c2 = (i & 31) * 2;
        size_t g = (size_t)(b * T_SEQ + tt * 64 + r) * DIM + h * HS + c2;
        *(unsigned*)&S[r][c2] = *(const unsigned*)&V[g];
    }
    __syncthreads();
#pragma unroll
    for (int i = tid; i < 64 * 32; i += 256) {
        int s = i >> 5, t2 = (i & 31) * 2;
        size_t g = (size_t)(bh * HS + s) * T_SEQ + tt * 64 + t2;
        *(unsigned*)&Vt[g] = pkh(S[t2][s], S[t2 + 1][s]);
    }
}

// ---------------- single-fp16 GEMM: 128x256x32, 512 thr, 3-stage (R11) -------
#define GP 40
#define GEMM_NKT 32
#define GEMM_STAGE (384 * GP)
#define GEMM_SMEM (3 * GEMM_STAGE * 2)      // 92160 B

__device__ __forceinline__ void gemm_body(
    const __half* __restrict__ A_, const __half* __restrict__ B_,
    float* __restrict__ Cf, __half* __restrict__ Ch, int mode, float scale,
    __half* gsm, int bm, int bn) {
    const int tid = threadIdx.x;
    const int lane = tid & 31, wid = tid >> 5;
    const int gid = lane >> 2, tig = lane & 3;
    const int wm = (wid & 3) * 32, wn = (wid >> 2) * 64;

    auto load_stage = [&](int stage, int kt) {
        const int k0 = kt * 32;
        __half* sb = gsm + stage * GEMM_STAGE;
#pragma unroll
        for (int i = tid; i < 1536; i += 512) {
            int r = i >> 2, c = i & 3;
            const __half* src = (r < 128)
                ? A_ + (size_t)(bm + r) * DIM + k0 + c * 8
                : B_ + (size_t)(bn + r - 128) * DIM + k0 + c * 8;
            cp16(sb + r * GP + c * 8, src);
        }
    };

    float acc[2][8][4];
#pragma unroll
    for (int mt = 0; mt < 2; mt++)
#pragma unroll
        for (int jn = 0; jn < 8; jn++)
#pragma unroll
            for (int e = 0; e < 4; e++) acc[mt][jn][e] = 0.f;

    load_stage(0, 0); CP_COMMIT();
    load_stage(1, 1); CP_COMMIT();

    for (int kt = 0; kt < GEMM_NKT; kt++) {
        if (kt + 2 < GEMM_NKT) load_stage((kt + 2) % 3, kt + 2);
        CP_COMMIT();
        CP_WAIT2();
        __syncthreads();

        const __half* st = gsm + (kt % 3) * GEMM_STAGE;
        const __half* As = st;
        const __half* Bs = st + 128 * GP;
#pragma unroll
        for (int kk = 0; kk < 2; kk++) {
            const int kc = kk * 16 + 2 * tig;
            unsigned af[2][4];
#pragma unroll
            for (int mt = 0; mt < 2; mt++) {
                int row = wm + 16 * mt + gid;
                af[mt][0] = *(const unsigned*)&As[row * GP + kc];
                af[mt][1] = *(const unsigned*)&As[(row + 8) * GP + kc];
                af[mt][2] = *(const unsigned*)&As[row * GP + kc + 8];
                af[mt][3] = *(const unsigned*)&As[(row + 8) * GP + kc + 8];
            }
#pragma unroll
            for (int jn = 0; jn < 8; jn++) {
                int n = wn + 8 * jn + gid;
                unsigned b0 = *(const unsigned*)&Bs[n * GP + kc];
                unsigned b1 = *(const unsigned*)&Bs[n * GP + kc + 8];
#pragma unroll
                for (int mt = 0; mt < 2; mt++)
                    mma16816h(acc[mt][jn], af[mt], b0, b1);
            }
        }
        __syncthreads();
    }

#pragma unroll
    for (int mt = 0; mt < 2; mt++) {
        int row0 = bm + wm + 16 * mt + gid;
#pragma unroll
        for (int jn = 0; jn < 8; jn++) {
            int col = bn + wn + 8 * jn + 2 * tig;
            float x0 = acc[mt][jn][0] * scale, x1 = acc[mt][jn][1] * scale;
            float x2 = acc[mt][jn][2] * scale, x3 = acc[mt][jn][3] * scale;
            if (mode == 0) {
                *(float2*)&Cf[(size_t)row0 * DIM + col] = make_float2(x0, x1);
                *(float2*)&Cf[(size_t)(row0 + 8) * DIM + col] = make_float2(x2, x3);
            } else {
                *(unsigned*)&Ch[(size_t)row0 * DIM + col] = pk2(x0, x1);
                *(unsigned*)&Ch[(size_t)(row0 + 8) * DIM + col] = pk2(x2, x3);
            }
        }
    }
}

__global__ __launch_bounds__(512, 1) void gemm_mma(
    const __half* __restrict__ A_, const __half* __restrict__ B_,
    float* __restrict__ Cf, __half* __restrict__ Ch, int mode, float scale) {
    extern __shared__ __half gsm[];
    gemm_body(A_, B_, Cf, Ch, mode, scale, gsm,
              blockIdx.y * 128, blockIdx.x * 256);
}

// merged K/V projection: z = 0 -> K = Xr@Wk ; z = 1 -> V = Xr@Wv
__global__ __launch_bounds__(512, 1) void gemm_kv(
    const __half* __restrict__ Xr_, const __half* __restrict__ WkT_,
    const __half* __restrict__ WvT_, __half* __restrict__ K_,
    __half* __restrict__ V_) {
    extern __shared__ __half gsm2[];
    const int z = blockIdx.z;
    gemm_body(Xr_, z ? WvT_ : WkT_, nullptr, z ? V_ : K_, 2, 1.0f, gsm2,
              blockIdx.y * 128, blockIdx.x * 256);
}

// ---------------- flash attention: single fp16, max-free (R11 structure) -----
#define AP 72
#define ATTN_NKT (T_SEQ / 64)
#define KV_STAGE (2 * 64 * AP)
#define ATTN_SMEM ((128 * AP + 4 * KV_STAGE) * 2)    // 92160 B

__global__ __launch_bounds__(256, 2) void attn_mma(
    const __half* __restrict__ Q_, const __half* __restrict__ K_,
    const __half* __restrict__ Vt_, const float* __restrict__ mask,
    __half* __restrict__ O_) {
    extern __shared__ __half asm_[];
    __half* Qs = asm_;
    __half* KV = Qs + 128 * AP;

    const int tid = threadIdx.x;
    const int lane = tid & 31, wid = tid >> 5;
    const int gid = lane >> 2, tig = lane & 3;
    const int bq = blockIdx.x, h = blockIdx.y, b = blockIdx.z;
    const int bh = b * NH + h;
    const int qrow0 = b * T_SEQ + bq * 128;

    auto load_kv = [&](int stage, int kt) {
        const int krow0 = b * T_SEQ + kt * 64;
        __half* sb = KV + stage * KV_STAGE;
#pragma unroll
        for (int i = tid; i < 1024; i += 256) {
            int a = i >> 9, r = (i >> 3) & 63, c = i & 7;
            __half* dst = sb + a * 64 * AP + r * AP + c * 8;
            if (a == 0)
                cp16(dst, K_ + (size_t)(krow0 + r) * DIM + h * HS + c * 8);
            else
                cp16(dst, Vt_ + (size_t)(bh * HS + r) * T_SEQ + kt * 64 + c * 8);
        }
    };

#pragma unroll
    for (int i = tid; i < 128 * 8; i += 256) {
        int r = i >> 3, c8 = (i & 7) * 8;
        *(int4*)&Qs[r * AP + c8] =
            *(const int4*)&Q_[(size_t)(qrow0 + r) * DIM + h * HS + c8];
    }

    load_kv(0, 0); CP_COMMIT();
    load_kv(1, 1); CP_COMMIT();
    load_kv(2, 2); CP_COMMIT();

    float li[2] = {0.f, 0.f};
    float accO[8][4];
#pragma unroll
    for (int jn = 0; jn < 8; jn++)
#pragma unroll
        for (int e = 0; e < 4; e++) accO[jn][e] = 0.f;

    const int q0g = bq * 128 + 16 * wid + gid;
    const float* mrow = mask + (size_t)bh * T_SEQ * T_SEQ;
    __syncthreads();   // Q visible

    for (int kt = 0; kt < ATTN_NKT; kt++) {
        if (kt + 3 < ATTN_NKT) load_kv((kt + 3) & 3, kt + 3);
        CP_COMMIT();

        float2 mr0[8], mr1[8];
#pragma unroll
        for (int jn = 0; jn < 8; jn++) {
            int c = kt * 64 + 8 * jn + 2 * tig;
            mr0[jn] = *(const float2*)&mrow[(size_t)q0g * T_SEQ + c];
            mr1[jn] = *(const float2*)&mrow[(size_t)(q0g + 8) * T_SEQ + c];
        }

        CP_WAIT3();
        __syncthreads();
        const __half* K_s = KV + (kt & 3) * KV_STAGE;
        const __half* V_s = K_s + 64 * AP;

        float sc[8][4];
#pragma unroll
        for (int jn = 0; jn < 8; jn++)
#pragma unroll
            for (int e = 0; e < 4; e++) sc[jn][e] = 0.f;
#pragma unroll
        for (int kk = 0; kk < 4; kk++) {
            const int kc = kk * 16 + 2 * tig;
            const int row = 16 * wid + gid;
            unsigned qa[4];
            qa[0] = *(const unsigned*)&Qs[row * AP + kc];
            qa[1] = *(const unsigned*)&Qs[(row + 8) * AP + kc];
            qa[2] = *(const unsigned*)&Qs[row * AP + kc + 8];
            qa[3] = *(const unsigned*)&Qs[(row + 8) * AP + kc + 8];
#pragma unroll
            for (int jn = 0; jn < 8; jn++) {
                int n = 8 * jn + gid;
                unsigned kf0 = *(const unsigned*)&K_s[n * AP + kc];
                unsigned kf1 = *(const unsigned*)&K_s[n * AP + kc + 8];
                mma16816h(sc[jn], qa, kf0, kf1);
            }
        }

        // mask + exp (max-free; masked scores underflow to 0)
        float rs0 = 0.f, rs1 = 0.f;
#pragma unroll
        for (int jn = 0; jn < 8; jn++) {
            sc[jn][0] = __expf(fmaf(mr0[jn].x, NEG_INF_F, sc[jn][0])); rs0 += sc[jn][0];
            sc[jn][1] = __expf(fmaf(mr0[jn].y, NEG_INF_F, sc[jn][1])); rs0 += sc[jn][1];
            sc[jn][2] = __expf(fmaf(mr1[jn].x, NEG_INF_F, sc[jn][2])); rs1 += sc[jn][2];
            sc[jn][3] = __expf(fmaf(mr1[jn].y, NEG_INF_F, sc[jn][3])); rs1 += sc[jn][3];
        }
        rs0 += __shfl_xor_sync(0xffffffffu, rs0, 1);
        rs0 += __shfl_xor_sync(0xffffffffu, rs0, 2);
        rs1 += __shfl_xor_sync(0xffffffffu, rs1, 1);
        rs1 += __shfl_xor_sync(0xffffffffu, rs1, 2);
        li[0] += rs0;
        li[1] += rs1;

        // accO += P @ V
#pragma unroll
        for (int kk2 = 0; kk2 < 4; kk2++) {
            const int j0 = 2 * kk2, j1 = 2 * kk2 + 1;
            unsigned pa[4];
            pa[0] = pk2(sc[j0][0], sc[j0][1]);
            pa[1] = pk2(sc[j0][2], sc[j0][3]);
            pa[2] = pk2(sc[j1][0], sc[j1][1]);
            pa[3] = pk2(sc[j1][2], sc[j1][3]);
            const int kc = kk2 * 16 + 2 * tig;
#pragma unroll
            for (int jn = 0; jn < 8; jn++) {
                int n = 8 * jn + gid;
                unsigned vf0 = *(const unsigned*)&V_s[n * AP + kc];
                unsigned vf1 = *(const unsigned*)&V_s[n * AP + kc + 8];
                mma16816h(accO[jn], pa, vf0, vf1);
            }
        }
        __syncthreads();
    }

    const float inv0 = 1.f / li[0], inv1 = 1.f / li[1];
    const int row0 = qrow0 + 16 * wid + gid;
#pragma unroll
    for (int jn = 0; jn < 8; jn++) {
        int col = h * HS + 8 * jn + 2 * tig;
        *(unsigned*)&O_[(size_t)row0 * DIM + col] =
            pk2(accO[jn][0] * inv0, accO[jn][1] * inv0);
        *(unsigned*)&O_[(size_t)(row0 + 8) * DIM + col] =
            pk2(accO[jn][2] * inv1, accO[jn][3] * inv1);
    }
}

// ---------------------------------------------------------------------------
extern "C" void kernel_launch(void* const* d_in, const int* in_sizes, int n_in,
                              void* d_out, int out_size) {
    const float* Xq   = (const float*)d_in[0];
    const float* Xr   = (const float*)d_in[1];
    const float* mask = (const float*)d_in[2];
    const float* Wq   = (const float*)d_in[3];
    const float* Wk   = (const float*)d_in[4];
    const float* Wv   = (const float*)d_in[5];
    const float* Wo   = (const float*)d_in[6];
    float* out = (float*)d_out;

    __half *Xq16, *Xr16, *WqT, *WkT, *WvT, *WoT;
    __half *Q16, *K16, *V16, *Vt16, *O16;
    cudaGetSymbolAddress((void**)&Xq16, g_Xq16); cudaGetSymbolAddress((void**)&Xr16, g_Xr16);
    cudaGetSymbolAddress((void**)&WqT, g_WqT);   cudaGetSymbolAddress((void**)&WkT, g_WkT);
    cudaGetSymbolAddress((void**)&WvT, g_WvT);   cudaGetSymbolAddress((void**)&WoT, g_WoT);
    cudaGetSymbolAddress((void**)&Q16, g_Q16);   cudaGetSymbolAddress((void**)&K16, g_K16);
    cudaGetSymbolAddress((void**)&V16, g_V16);   cudaGetSymbolAddress((void**)&Vt16, g_Vt16);
    cudaGetSymbolAddress((void**)&O16, g_O16);

    cudaFuncSetAttribute(attn_mma, cudaFuncAttributeMaxDynamicSharedMemorySize, ATTN_SMEM);
    cudaFuncSetAttribute(gemm_mma, cudaFuncAttributeMaxDynamicSharedMemorySize, GEMM_SMEM);
    cudaFuncSetAttribute(gemm_kv, cudaFuncAttributeMaxDynamicSharedMemorySize, GEMM_SMEM);

    dim3 gg(DIM / 256, NT_ROWS / 128);          // 128 CTAs
    dim3 ggkv(DIM / 256, NT_ROWS / 128, 2);     // K and V in one launch

    split_x_all<<<dim3(NELEM / 1024, 2), 256>>>(Xq, Xr, Xq16, Xr16);
    split_wT_all<<<dim3(32, 32, 4), 256>>>(Wq, Wk, Wv, Wo, WqT, WkT, WvT, WoT);
    gemm_kv<<<ggkv, 512, GEMM_SMEM>>>(Xr16, WkT, WvT, K16, V16);
    transpose_v<<<dim3(T_SEQ / 64, NB * NH), 256>>>(V16, Vt16);
    gemm_mma<<<gg, 512, GEMM_SMEM>>>(Xq16, WqT, nullptr, Q16, 2, 0.125f);
    attn_mma<<<dim3(T_SEQ / 128, NH, NB), 256, ATTN_SMEM>>>(
        Q16, K16, Vt16, mask, O16);
    gemm_mma<<<gg, 512, GEMM_SMEM>>>(O16, WoT, out, nullptr, 0, 1.0f);
}

// round 16
// speedup vs baseline: 1.4437x; 1.0131x over previous
#include <cuda_runtime.h>
#include <cuda_fp16.h>
#include <cstdint>

#define T_SEQ 2048
#define NB 2
#define DIM 1024
#define NH 16
#define HS 64
#define NT_ROWS 4096
#define NEG_INF_F (-1e9f)
#define NELEM (NT_ROWS * DIM)

// ---------------- scratch (__device__ globals: allocation-free rule) --------
__device__ __half g_Xq16[NELEM];
__device__ __half g_Xr16[NELEM];
__device__ __half g_WqT[DIM * DIM];
__device__ __half g_WkT[DIM * DIM];
__device__ __half g_WvT[DIM * DIM];
__device__ __half g_WoT[DIM * DIM];
__device__ __half g_Q16[NELEM];
__device__ __half g_K16[NELEM];
__device__ __half g_Vt16[NELEM];
__device__ __half g_O16[NELEM];

// ---------------- helpers ---------------------------------------------------
__device__ __forceinline__ unsigned pk2(float x0, float x1) {
    __half2 h = __float22half2_rn(make_float2(x0, x1));   // one cvt.rn.f16x2.f32
    return *(unsigned*)&h;
}
__device__ __forceinline__ void mma16816h(float (&d)[4], const unsigned (&a)[4],
                                          unsigned b0, unsigned b1) {
    asm volatile(
        "mma.sync.aligned.m16n8k16.row.col.f32.f16.f16.f32 "
        "{%0,%1,%2,%3}, {%4,%5,%6,%7}, {%8,%9}, {%0,%1,%2,%3};"
        : "+f"(d[0]), "+f"(d[1]), "+f"(d[2]), "+f"(d[3])
        : "r"(a[0]), "r"(a[1]), "r"(a[2]), "r"(a[3]), "r"(b0), "r"(b1));
}
__device__ __forceinline__ uint32_t smem_u32(const void* p) {
    uint32_t a;
    asm("{ .reg .u64 t; cvta.to.shared.u64 t, %1; cvt.u32.u64 %0, t; }" : "=r"(a) : "l"(p));
    return a;
}
__device__ __forceinline__ void cp16(void* smem_dst, const void* gsrc) {
    uint32_t s = smem_u32(smem_dst);
    asm volatile("cp.async.cg.shared.global [%0], [%1], 16;" :: "r"(s), "l"(gsrc) : "memory");
}
#define CP_COMMIT() asm volatile("cp.async.commit_group;" ::: "memory")
#define CP_WAIT2() asm volatile("cp.async.wait_group 2;" ::: "memory")
#define CP_WAIT3() asm volatile("cp.async.wait_group 3;" ::: "memory")

// ---------------- split kernels ----------------------------------------------
__global__ __launch_bounds__(256) void split_x_all(
    const float* __restrict__ Xq, const float* __restrict__ Xr,
    __half* __restrict__ Xq16, __half* __restrict__ Xr16) {
    const int z = blockIdx.y;
    const float* X = z ? Xr : Xq;
    __half* Xo = z ? Xr16 : Xq16;
    size_t i = ((size_t)blockIdx.x * 256 + threadIdx.x) * 4;
    float4 v = *(const float4*)(X + i);
    *(unsigned*)&Xo[i]     = pk2(v.x, v.y);
    *(unsigned*)&Xo[i + 2] = pk2(v.z, v.w);
}

__global__ __launch_bounds__(256) void split_wT_all(
    const float* __restrict__ W0, const float* __restrict__ W1,
    const float* __restrict__ W2, const float* __restrict__ W3,
    __half* __restrict__ T0, __half* __restrict__ T1,
    __half* __restrict__ T2, __half* __restrict__ T3) {
    const int z = blockIdx.z;
    const float* W = (z == 0) ? W0 : (z == 1) ? W1 : (z == 2) ? W2 : W3;
    __half* Wt = (z == 0) ? T0 : (z == 1) ? T1 : (z == 2) ? T2 : T3;
    __shared__ float S[32][33];
    const int n0 = blockIdx.x * 32, k0 = blockIdx.y * 32;
    const int tid = threadIdx.x;
#pragma unroll
    for (int i = tid; i < 1024; i += 256) {
        int r = i >> 5, c = i & 31;
        S[r][c] = W[(size_t)(k0 + r) * DIM + n0 + c];
    }
    __syncthreads();
#pragma unroll
    for (int i = tid; i < 1024; i += 256) {
        int rr = i >> 5, cc = i & 31;
        Wt[(size_t)(n0 + rr) * DIM + k0 + cc] = __float2half_rn(S[cc][rr]);
    }
}

// ---------------- single-fp16 GEMM: 128x256x32, 512 thr, 3-stage -------------
// modes: 0 = fp32 out; 2 = fp16 out (row-major); 3 = fp16 out, V-transposed:
//   Vt[(b*16 + col/64)*64 + col%64][token] <- C[row][col]
#define GP 40
#define GEMM_NKT 32
#define GEMM_STAGE (384 * GP)
#define GEMM_SMEM (3 * GEMM_STAGE * 2)      // 92160 B

__device__ __forceinline__ void gemm_body(
    const __half* __restrict__ A_, const __half* __restrict__ B_,
    float* __restrict__ Cf, __half* __restrict__ Ch, int mode, float scale,
    __half* gsm, int bm, int bn) {
    const int tid = threadIdx.x;
    const int lane = tid & 31, wid = tid >> 5;
    const int gid = lane >> 2, tig = lane & 3;
    const int wm = (wid & 3) * 32, wn = (wid >> 2) * 64;

    auto load_stage = [&](int stage, int kt) {
        const int k0 = kt * 32;
        __half* sb = gsm + stage * GEMM_STAGE;
#pragma unroll
        for (int i = tid; i < 1536; i += 512) {
            int r = i >> 2, c = i & 3;
            const __half* src = (r < 128)
                ? A_ + (size_t)(bm + r) * DIM + k0 + c * 8
                : B_ + (size_t)(bn + r - 128) * DIM + k0 + c * 8;
            cp16(sb + r * GP + c * 8, src);
        }
    };

    float acc[2][8][4];
#pragma unroll
    for (int mt = 0; mt < 2; mt++)
#pragma unroll
        for (int jn = 0; jn < 8; jn++)
#pragma unroll
            for (int e = 0; e < 4; e++) acc[mt][jn][e] = 0.f;

    load_stage(0, 0); CP_COMMIT();
    load_stage(1, 1); CP_COMMIT();

    for (int kt = 0; kt < GEMM_NKT; kt++) {
        if (kt + 2 < GEMM_NKT) load_stage((kt + 2) % 3, kt + 2);
        CP_COMMIT();
        CP_WAIT2();
        __syncthreads();

        const __half* st = gsm + (kt % 3) * GEMM_STAGE;
        const __half* As = st;
        const __half* Bs = st + 128 * GP;
#pragma unroll
        for (int kk = 0; kk < 2; kk++) {
            const int kc = kk * 16 + 2 * tig;
            unsigned af[2][4];
#pragma unroll
            for (int mt = 0; mt < 2; mt++) {
                int row = wm + 16 * mt + gid;
                af[mt][0] = *(const unsigned*)&As[row * GP + kc];
                af[mt][1] = *(const unsigned*)&As[(row + 8) * GP + kc];
                af[mt][2] = *(const unsigned*)&As[row * GP + kc + 8];
                af[mt][3] = *(const unsigned*)&As[(row + 8) * GP + kc + 8];
            }
#pragma unroll
            for (int jn = 0; jn < 8; jn++) {
                int n = wn + 8 * jn + gid;
                unsigned b0 = *(const unsigned*)&Bs[n * GP + kc];
                unsigned b1 = *(const unsigned*)&Bs[n * GP + kc + 8];
#pragma unroll
                for (int mt = 0; mt < 2; mt++)
                    mma16816h(acc[mt][jn], af[mt], b0, b1);
            }
        }
        __syncthreads();
    }

#pragma unroll
    for (int mt = 0; mt < 2; mt++) {
        int row0 = bm + wm + 16 * mt + gid;
#pragma unroll
        for (int jn = 0; jn < 8; jn++) {
            int col = bn + wn + 8 * jn + 2 * tig;
            float x0 = acc[mt][jn][0] * scale, x1 = acc[mt][jn][1] * scale;
            float x2 = acc[mt][jn][2] * scale, x3 = acc[mt][jn][3] * scale;
            if (mode == 0) {
                *(float2*)&Cf[(size_t)row0 * DIM + col] = make_float2(x0, x1);
                *(float2*)&Cf[(size_t)(row0 + 8) * DIM + col] = make_float2(x2, x3);
            } else if (mode == 2) {
                *(unsigned*)&Ch[(size_t)row0 * DIM + col] = pk2(x0, x1);
                *(unsigned*)&Ch[(size_t)(row0 + 8) * DIM + col] = pk2(x2, x3);
            } else {
                // mode 3: direct transposed V write.
                // row = b*2048 + token; col = h*64 + s (s even; s+1 same head)
                const int b = row0 >> 11, t = row0 & 2047;
                const int h = col >> 6, s = col & 63;
                __half* vbase = Ch + ((size_t)(((b << 4) + h) * HS + s)) * T_SEQ;
                vbase[t]                 = __float2half_rn(x0);   // (s,   row0)
                vbase[T_SEQ + t]         = __float2half_rn(x1);   // (s+1, row0)
                vbase[t + 8]             = __float2half_rn(x2);   // (s,   row0+8)
                vbase[T_SEQ + t + 8]     = __float2half_rn(x3);   // (s+1, row0+8)
            }
        }
    }
}

__global__ __launch_bounds__(512, 1) void gemm_mma(
    const __half* __restrict__ A_, const __half* __restrict__ B_,
    float* __restrict__ Cf, __half* __restrict__ Ch, int mode, float scale) {
    extern __shared__ __half gsm[];
    gemm_body(A_, B_, Cf, Ch, mode, scale, gsm,
              blockIdx.y * 128, blockIdx.x * 256);
}

// merged K/V projection: z = 0 -> K (row-major) ; z = 1 -> V (transposed out)
__global__ __launch_bounds__(512, 1) void gemm_kv(
    const __half* __restrict__ Xr_, const __half* __restrict__ WkT_,
    const __half* __restrict__ WvT_, __half* __restrict__ K_,
    __half* __restrict__ Vt_) {
    extern __shared__ __half gsm2[];
    const int z = blockIdx.z;
    gemm_body(Xr_, z ? WvT_ : WkT_, nullptr, z ? Vt_ : K_, z ? 3 : 2, 1.0f,
              gsm2, blockIdx.y * 128, blockIdx.x * 256);
}

// ---------------- flash attention: single fp16, max-free (R11 structure) -----
#define AP 72
#define ATTN_NKT (T_SEQ / 64)
#define KV_STAGE (2 * 64 * AP)
#define ATTN_SMEM ((128 * AP + 4 * KV_STAGE) * 2)    // 92160 B

__global__ __launch_bounds__(256, 2) void attn_mma(
    const __half* __restrict__ Q_, const __half* __restrict__ K_,
    const __half* __restrict__ Vt_, const float* __restrict__ mask,
    __half* __restrict__ O_) {
    extern __shared__ __half asm_[];
    __half* Qs = asm_;
    __half* KV = Qs + 128 * AP;

    const int tid = threadIdx.x;
    const int lane = tid & 31, wid = tid >> 5;
    const int gid = lane >> 2, tig = lane & 3;
    const int bq = blockIdx.x, h = blockIdx.y, b = blockIdx.z;
    const int bh = b * NH + h;
    const int qrow0 = b * T_SEQ + bq * 128;

    auto load_kv = [&](int stage, int kt) {
        const int krow0 = b * T_SEQ + kt * 64;
        __half* sb = KV + stage * KV_STAGE;
#pragma unroll
        for (int i = tid; i < 1024; i += 256) {
            int a = i >> 9, r = (i >> 3) & 63, c = i & 7;
            __half* dst = sb + a * 64 * AP + r * AP + c * 8;
            if (a == 0)
                cp16(dst, K_ + (size_t)(krow0 + r) * DIM + h * HS + c * 8);
            else
                cp16(dst, Vt_ + (size_t)(bh * HS + r) * T_SEQ + kt * 64 + c * 8);
        }
    };

#pragma unroll
    for (int i = tid; i < 128 * 8; i += 256) {
        int r = i >> 3, c8 = (i & 7) * 8;
        *(int4*)&Qs[r * AP + c8] =
            *(const int4*)&Q_[(size_t)(qrow0 + r) * DIM + h * HS + c8];
    }

    load_kv(0, 0); CP_COMMIT();
    load_kv(1, 1); CP_COMMIT();
    load_kv(2, 2); CP_COMMIT();

    float li[2] = {0.f, 0.f};
    float accO[8][4];
#pragma unroll
    for (int jn = 0; jn < 8; jn++)
#pragma unroll
        for (int e = 0; e < 4; e++) accO[jn][e] = 0.f;

    const int q0g = bq * 128 + 16 * wid + gid;
    const float* mrow = mask + (size_t)bh * T_SEQ * T_SEQ;
    __syncthreads();   // Q visible

    for (int kt = 0; kt < ATTN_NKT; kt++) {
        if (kt + 3 < ATTN_NKT) load_kv((kt + 3) & 3, kt + 3);
        CP_COMMIT();

        float2 mr0[8], mr1[8];
#pragma unroll
        for (int jn = 0; jn < 8; jn++) {
            int c = kt * 64 + 8 * jn + 2 * tig;
            mr0[jn] = *(const float2*)&mrow[(size_t)q0g * T_SEQ + c];
            mr1[jn] = *(const float2*)&mrow[(size_t)(q0g + 8) * T_SEQ + c];
        }

        CP_WAIT3();
        __syncthreads();
        const __half* K_s = KV + (kt & 3) * KV_STAGE;
        const __half* V_s = K_s + 64 * AP;

        float sc[8][4];
#pragma unroll
        for (int jn = 0; jn < 8; jn++)
#pragma unroll
            for (int e = 0; e < 4; e++) sc[jn][e] = 0.f;
#pragma unroll
        for (int kk = 0; kk < 4; kk++) {
            const int kc = kk * 16 + 2 * tig;
            const int row = 16 * wid + gid;
            unsigned qa[4];
            qa[0] = *(const unsigned*)&Qs[row * AP + kc];
            qa[1] = *(const unsigned*)&Qs[(row + 8) * AP + kc];
            qa[2] = *(const unsigned*)&Qs[row * AP + kc + 8];
            qa[3] = *(const unsigned*)&Qs[(row + 8) * AP + kc + 8];
#pragma unroll
            for (int jn = 0; jn < 8; jn++) {
                int n = 8 * jn + gid;
                unsigned kf0 = *(const unsigned*)&K_s[n * AP + kc];
                unsigned kf1 = *(const unsigned*)&K_s[n * AP + kc + 8];
                mma16816h(sc[jn], qa, kf0, kf1);
            }
        }

        // mask + exp (max-free; masked scores underflow to 0)
        float rs0 = 0.f, rs1 = 0.f;
#pragma unroll
        for (int jn = 0; jn < 8; jn++) {
            sc[jn][0] = __expf(fmaf(mr0[jn].x, NEG_INF_F, sc[jn][0])); rs0 += sc[jn][0];
            sc[jn][1] = __expf(fmaf(mr0[jn].y, NEG_INF_F, sc[jn][1])); rs0 += sc[jn][1];
            sc[jn][2] = __expf(fmaf(mr1[jn].x, NEG_INF_F, sc[jn][2])); rs1 += sc[jn][2];
            sc[jn][3] = __expf(fmaf(mr1[jn].y, NEG_INF_F, sc[jn][3])); rs1 += sc[jn][3];
        }
        rs0 += __shfl_xor_sync(0xffffffffu, rs0, 1);
        rs0 += __shfl_xor_sync(0xffffffffu, rs0, 2);
        rs1 += __shfl_xor_sync(0xffffffffu, rs1, 1);
        rs1 += __shfl_xor_sync(0xffffffffu, rs1, 2);
        li[0] += rs0;
        li[1] += rs1;

        // accO += P @ V
#pragma unroll
        for (int kk2 = 0; kk2 < 4; kk2++) {
            const int j0 = 2 * kk2, j1 = 2 * kk2 + 1;
            unsigned pa[4];
            pa[0] = pk2(sc[j0][0], sc[j0][1]);
            pa[1] = pk2(sc[j0][2], sc[j0][3]);
            pa[2] = pk2(sc[j1][0], sc[j1][1]);
            pa[3] = pk2(sc[j1][2], sc[j1][3]);
            const int kc = kk2 * 16 + 2 * tig;
#pragma unroll
            for (int jn = 0; jn < 8; jn++) {
                int n = 8 * jn + gid;
                unsigned vf0 = *(const unsigned*)&V_s[n * AP + kc];
                unsigned vf1 = *(const unsigned*)&V_s[n * AP + kc + 8];
                mma16816h(accO[jn], pa, vf0, vf1);
            }
        }
        __syncthreads();
    }

    const float inv0 = 1.f / li[0], inv1 = 1.f / li[1];
    const int row0 = qrow0 + 16 * wid + gid;
#pragma unroll
    for (int jn = 0; jn < 8; jn++) {
        int col = h * HS + 8 * jn + 2 * tig;
        *(unsigned*)&O_[(size_t)row0 * DIM + col] =
            pk2(accO[jn][0] * inv0, accO[jn][1] * inv0);
        *(unsigned*)&O_[(size_t)(row0 + 8) * DIM + col] =
            pk2(accO[jn][2] * inv1, accO[jn][3] * inv1);
    }
}

// ---------------------------------------------------------------------------
extern "C" void kernel_launch(void* const* d_in, const int* in_sizes, int n_in,
                              void* d_out, int out_size) {
    const float* Xq   = (const float*)d_in[0];
    const float* Xr   = (const float*)d_in[1];
    const float* mask = (const float*)d_in[2];
    const float* Wq   = (const float*)d_in[3];
    const float* Wk   = (const float*)d_in[4];
    const float* Wv   = (const float*)d_in[5];
    const float* Wo   = (const float*)d_in[6];
    float* out = (float*)d_out;

    __half *Xq16, *Xr16, *WqT, *WkT, *WvT, *WoT;
    __half *Q16, *K16, *Vt16, *O16;
    cudaGetSymbolAddress((void**)&Xq16, g_Xq16); cudaGetSymbolAddress((void**)&Xr16, g_Xr16);
    cudaGetSymbolAddress((void**)&WqT, g_WqT);   cudaGetSymbolAddress((void**)&WkT, g_WkT);
    cudaGetSymbolAddress((void**)&WvT, g_WvT);   cudaGetSymbolAddress((void**)&WoT, g_WoT);
    cudaGetSymbolAddress((void**)&Q16, g_Q16);   cudaGetSymbolAddress((void**)&K16, g_K16);
    cudaGetSymbolAddress((void**)&Vt16, g_Vt16); cudaGetSymbolAddress((void**)&O16, g_O16);

    cudaFuncSetAttribute(attn_mma, cudaFuncAttributeMaxDynamicSharedMemorySize, ATTN_SMEM);
    cudaFuncSetAttribute(gemm_mma, cudaFuncAttributeMaxDynamicSharedMemorySize, GEMM_SMEM);
    cudaFuncSetAttribute(gemm_kv, cudaFuncAttributeMaxDynamicSharedMemorySize, GEMM_SMEM);

    dim3 gg(DIM / 256, NT_ROWS / 128);          // 128 CTAs
    dim3 ggkv(DIM / 256, NT_ROWS / 128, 2);     // K and V in one launch

    split_x_all<<<dim3(NELEM / 1024, 2), 256>>>(Xq, Xr, Xq16, Xr16);
    split_wT_all<<<dim3(32, 32, 4), 256>>>(Wq, Wk, Wv, Wo, WqT, WkT, WvT, WoT);
    gemm_kv<<<ggkv, 512, GEMM_SMEM>>>(Xr16, WkT, WvT, K16, Vt16);   // V transposed in epilogue
    gemm_mma<<<gg, 512, GEMM_SMEM>>>(Xq16, WqT, nullptr, Q16, 2, 0.125f);
    attn_mma<<<dim3(T_SEQ / 128, NH, NB), 256, ATTN_SMEM>>>(
        Q16, K16, Vt16, mask, O16);
    gemm_mma<<<gg, 512, GEMM_SMEM>>>(O16, WoT, out, nullptr, 0, 1.0f);
}